// round 16
// baseline (speedup 1.0000x reference)
#include <cuda_runtime.h>
#include <cstdint>

// LDDMM variational shooting RHS, Gaussian kernel sigma=0.1, B=1, N=8192, D=3.
//
// dcp_i  = sum_j exp(-50*|xi-xj|^2) * p_j                    (p = clamp(mom,-1,1))
// dmom_i = 100 * ( x_i * sum_j W_ij  -  sum_j W_ij x_j ),  W_ij = K_ij (p_i.p_j)
//
// O(N^2) pairwise with fma.rn.f32x2 (2 j per instr): 15 FMA2 + 2 MUFU per
// (2j x 1i). IPT=1, regs<=64, 8 blocks/SM, grid 64x16 = one wave.
// THIS ROUND: a tiny prep kernel packs {scaled coords, -|x|^2, clamped p} into
// the exact packed-f32x2 tile layout in global memory ONCE; main blocks load
// their 14KB j-tile as pure coalesced vector copies (prologue ~3x shorter,
// no div/mod/clamp in the main kernel). Reduction tail gets MLP via unroll.
//   d2n = 2 xi.xj - |xi|^2 - |xj|^2  (coords pre-scaled by s=sqrt(50 log2 e))
//   K   = ex2.approx(d2n) per lane   (MUFU, underflow->0 = free clamp)
// Cross-g reduction fused: last block per i-column (atomic counter) sums the
// per-g partials in fixed order (deterministic) and writes the output.

#define THREADS 128
#define ISPAN   THREADS           // 128 i per block (IPT=1)
#define JTILE   512               // j per block -> 64 x 16 = 1024 blocks = one wave
#define JT2     (JTILE / 2)       // packed j-pairs in tile
#define MAXN    16384
#define MAXN2   (MAXN / 2)
#define MAXG    ((MAXN + JTILE - 1) / JTILE)
#define MAXBI   (MAXN / ISPAN)

// coordinate prescale: s^2 = 50*log2(e) = 72.13475204
#define SSCALE  8.4932180f

using u64 = unsigned long long;

// packed j data, tile layout: index k = pair of points (2k, 2k+1)
__device__ __align__(16) ulonglong2 g_jA[MAXN2];  // (xj, yj)   scaled
__device__ __align__(16) ulonglong2 g_jB[MAXN2];  // (zj, nsqj) nsqj = -|xj_s|^2
__device__ __align__(16) ulonglong2 g_jC[MAXN2];  // (qx, qy)   clamped momenta
__device__                u64        g_jD[MAXN2];  // qz

// partials: g_part[g][d*MAXN + i]; d=0..2: sum e*p_j ; d=3..5: sum w*x_j ; d=6: sum w
__device__ __align__(16) float g_part[MAXG][7 * MAXN];
__device__ int g_cnt[MAXBI];       // zero-init; self-resetting per launch

__device__ __forceinline__ u64 pk2(float a, float b) {
    u64 r; asm("mov.b64 %0, {%1, %2};" : "=l"(r) : "f"(a), "f"(b)); return r;
}
__device__ __forceinline__ void upk2(u64 v, float& a, float& b) {
    asm("mov.b64 {%0, %1}, %2;" : "=f"(a), "=f"(b) : "l"(v));
}
__device__ __forceinline__ u64 f2add(u64 a, u64 b) {
    u64 r; asm("add.rn.f32x2 %0, %1, %2;" : "=l"(r) : "l"(a), "l"(b)); return r;
}
__device__ __forceinline__ u64 f2mul(u64 a, u64 b) {
    u64 r; asm("mul.rn.f32x2 %0, %1, %2;" : "=l"(r) : "l"(a), "l"(b)); return r;
}
__device__ __forceinline__ u64 f2fma(u64 a, u64 b, u64 c) {
    u64 r; asm("fma.rn.f32x2 %0, %1, %2, %3;" : "=l"(r) : "l"(a), "l"(b), "l"(c)); return r;
}
__device__ __forceinline__ float ex2a(float v) {
    float r; asm("ex2.approx.f32 %0, %1;" : "=f"(r) : "f"(v)); return r;
}
__device__ __forceinline__ float clamp1(float v) {
    return fminf(fmaxf(v, -1.0f), 1.0f);
}

// ---- prep: pack j data into tile layout (pad region zeroed) ----
__global__ void lddmm_prep(const float* __restrict__ mom, const float* __restrict__ x,
                           int N, int NPAD2)   // NPAD2 = padded pair count
{
    int k = blockIdx.x * blockDim.x + threadIdx.x;
    if (k >= NPAD2) return;
    int j0 = 2 * k, j1 = j0 + 1;
    float X0 = 0.f, Y0 = 0.f, Z0 = 0.f, P0 = 0.f, Q0 = 0.f, R0 = 0.f;
    float X1 = 0.f, Y1 = 0.f, Z1 = 0.f, P1 = 0.f, Q1 = 0.f, R1 = 0.f;
    if (j0 < N) {
        X0 = x[3 * j0] * SSCALE; Y0 = x[3 * j0 + 1] * SSCALE; Z0 = x[3 * j0 + 2] * SSCALE;
        P0 = clamp1(mom[3 * j0]); Q0 = clamp1(mom[3 * j0 + 1]); R0 = clamp1(mom[3 * j0 + 2]);
    }
    if (j1 < N) {
        X1 = x[3 * j1] * SSCALE; Y1 = x[3 * j1 + 1] * SSCALE; Z1 = x[3 * j1 + 2] * SSCALE;
        P1 = clamp1(mom[3 * j1]); Q1 = clamp1(mom[3 * j1 + 1]); R1 = clamp1(mom[3 * j1 + 2]);
    }
    float S0 = -(X0 * X0 + Y0 * Y0 + Z0 * Z0);
    float S1 = -(X1 * X1 + Y1 * Y1 + Z1 * Z1);
    ulonglong2 v;
    v.x = pk2(X0, X1); v.y = pk2(Y0, Y1); g_jA[k] = v;
    v.x = pk2(Z0, Z1); v.y = pk2(S0, S1); g_jB[k] = v;
    v.x = pk2(P0, P1); v.y = pk2(Q0, Q1); g_jC[k] = v;
    g_jD[k] = pk2(R0, R1);
}

__global__ __launch_bounds__(THREADS, 8)
void lddmm_main(const float* __restrict__ mom, const float* __restrict__ x,
                float* __restrict__ out, int N)
{
    __shared__ ulonglong2 sT0[JT2];
    __shared__ ulonglong2 sT1[JT2];
    __shared__ ulonglong2 sT2[JT2];
    __shared__ u64        sQz[JT2];
    __shared__ int        sLast;

    const int t  = threadIdx.x;
    const int bi = blockIdx.x;
    const int g  = blockIdx.y;
    const int G  = gridDim.y;
    const int kbase = g * JT2;   // packed-pair offset of this tile

    // ---- tile load: pure coalesced vector copy (8 independent LDG / thread) ----
#pragma unroll
    for (int k = t; k < JT2; k += THREADS) {
        sT0[k] = g_jA[kbase + k];
        sT1[k] = g_jB[kbase + k];
        sT2[k] = g_jC[kbase + k];
        sQz[k] = g_jD[kbase + k];
    }

    // ---- per-thread i state (overlaps with tile LDGs; sync after) ----
    const int i = bi * ISPAN + t;
    float X = 0.f, Y = 0.f, Z = 0.f, P = 0.f, Q = 0.f, R = 0.f;
    if (i < N) {
        X = x[3 * i] * SSCALE; Y = x[3 * i + 1] * SSCALE; Z = x[3 * i + 2] * SSCALE;
        P = clamp1(mom[3 * i]); Q = clamp1(mom[3 * i + 1]); R = clamp1(mom[3 * i + 2]);
    }
    const float S = -(X * X + Y * Y + Z * Z);
    const u64 p2x = pk2(2.f * X, 2.f * X);
    const u64 p2y = pk2(2.f * Y, 2.f * Y);
    const u64 p2z = pk2(2.f * Z, 2.f * Z);
    const u64 nsqi = pk2(S, S);
    const u64 pxi = pk2(P, P), pyi = pk2(Q, Q), pzi = pk2(R, R);

    u64 acx = 0ull, acy = 0ull, acz = 0ull;   // sum e * p_j
    u64 awx = 0ull, awy = 0ull, awz = 0ull;   // sum w * xj_s
    u64 aw  = 0ull;                            // sum w

    __syncthreads();

    // ---- main pairwise loop: each iter = 2 j x 1 i ----
#pragma unroll 8
    for (int k = 0; k < JT2; k++) {
        ulonglong2 t0 = sT0[k], t1 = sT1[k], t2 = sT2[k];
        u64 xj = t0.x, yj = t0.y, zj = t1.x, nsqj = t1.y;
        u64 qx = t2.x, qy = t2.y, qz = sQz[k];

        u64 d2n = f2add(nsqj, nsqi);            // -(|xi|^2 + |xj|^2)
        d2n = f2fma(p2x, xj, d2n);
        d2n = f2fma(p2y, yj, d2n);
        d2n = f2fma(p2z, zj, d2n);              // = -50*log2(e)*|xi-xj|^2 <= 0
        float a, b; upk2(d2n, a, b);
        u64 e = pk2(ex2a(a), ex2a(b));          // K_ij = 2^(d2n)  (MUFU)

        u64 pp = f2mul(pxi, qx);
        pp = f2fma(pyi, qy, pp);
        pp = f2fma(pzi, qz, pp);                // p_i . p_j
        u64 w = f2mul(e, pp);                   // W_ij

        acx = f2fma(e, qx, acx);
        acy = f2fma(e, qy, acy);
        acz = f2fma(e, qz, acz);
        awx = f2fma(w, xj, awx);
        awy = f2fma(w, yj, awy);
        awz = f2fma(w, zj, awz);
        aw  = f2add(aw, w);
    }

    // ---- write partials, coalesced [g][d][i] (one writer per slot) ----
    if (i < N) {
        float u, v;
        float* Pp = g_part[g];
        upk2(acx, u, v); Pp[0 * MAXN + i] = u + v;
        upk2(acy, u, v); Pp[1 * MAXN + i] = u + v;
        upk2(acz, u, v); Pp[2 * MAXN + i] = u + v;
        upk2(awx, u, v); Pp[3 * MAXN + i] = u + v;
        upk2(awy, u, v); Pp[4 * MAXN + i] = u + v;
        upk2(awz, u, v); Pp[5 * MAXN + i] = u + v;
        upk2(aw , u, v); Pp[6 * MAXN + i] = u + v;
    }

    // ---- fused cross-g reduction: last block of this i-column does it ----
    __threadfence();
    if (t == 0) {
        int old = atomicAdd(&g_cnt[bi], 1);
        sLast = (old == G - 1) ? 1 : 0;
    }
    __syncthreads();
    if (sLast) {
        const float DCA = -100.0f / SSCALE;   // for sum(w*xj_s): unscale + sign
        if (i < N) {
            float a0 = 0.f, a1 = 0.f, a2 = 0.f, a3 = 0.f, a4 = 0.f, a5 = 0.f, a6 = 0.f;
#pragma unroll 4
            for (int gg = 0; gg < G; gg++) {   // fixed order -> deterministic
                const float* Pp = g_part[gg];
                a0 += Pp[0 * MAXN + i]; a1 += Pp[1 * MAXN + i]; a2 += Pp[2 * MAXN + i];
                a3 += Pp[3 * MAXN + i]; a4 += Pp[4 * MAXN + i]; a5 += Pp[5 * MAXN + i];
                a6 += Pp[6 * MAXN + i];
            }
            // dcp
            out[3 * N + 3 * i + 0] = a0;
            out[3 * N + 3 * i + 1] = a1;
            out[3 * N + 3 * i + 2] = a2;
            // dmom = 100*( x_i * SumW - Sum(w x_j) )   (a3..a5 carry scale s)
            out[3 * i + 0] = 100.0f * x[3 * i + 0] * a6 + DCA * a3;
            out[3 * i + 1] = 100.0f * x[3 * i + 1] * a6 + DCA * a4;
            out[3 * i + 2] = 100.0f * x[3 * i + 2] * a6 + DCA * a5;
        }
        __syncthreads();
        if (t == 0) g_cnt[bi] = 0;   // self-reset for next (graph) replay
    }
}

extern "C" void kernel_launch(void* const* d_in, const int* in_sizes, int n_in,
                              void* d_out, int out_size)
{
    const float* mom = (const float*)d_in[0];
    const float* x   = (const float*)d_in[1];
    int N = in_sizes[0] / 3;
    if (N <= 0) return;
    if (N > MAXN) N = MAXN;  // scratch bound (problem uses N=8192)

    int G     = (N + JTILE - 1) / JTILE;
    int NBI   = (N + ISPAN - 1) / ISPAN;
    int NPAD2 = G * JT2;     // packed pairs incl. padding

    lddmm_prep<<<(NPAD2 + 255) / 256, 256>>>(mom, x, N, NPAD2);

    dim3 grid(NBI, G);
    lddmm_main<<<grid, THREADS>>>(mom, x, (float*)d_out, N);
}